// round 1
// baseline (speedup 1.0000x reference)
#include <cuda_runtime.h>
#include <cstdint>

// ---------------------------------------------------------------------------
// Scratch: FPS index buffer (max level-1 size: 8 batches x 4096 points)
// ---------------------------------------------------------------------------
__device__ int g_fps_idx[8 * 4096];

// ---------------------------------------------------------------------------
// Furthest point sampling.
// One block per batch, 1024 threads, persistent. Point coords live in
// registers (K = N/1024 per thread); an SMEM copy of xyz serves the per-
// iteration broadcast of the newly selected point.
// Arithmetic matches the JAX reference: d = dx*dx + dy*dy + dz*dz (nvcc
// contracts to FMUL+FFMA+FFMA), dists = fminf(dists, d), argmax with
// first-occurrence (lowest index) tie-break like jnp.argmax.
// ---------------------------------------------------------------------------
template <int N, int K>
__global__ __launch_bounds__(1024, 1)
void fps_kernel(const float* __restrict__ pts, int C, int npoints,
                int* __restrict__ idx_out)
{
    extern __shared__ float sm[];
    float* sx = sm;
    float* sy = sm + N;
    float* sz = sm + 2 * N;
    float* rv = sm + 3 * N;          // 32 warp-reduction values
    int*   ri = (int*)(rv + 32);     // 32 warp-reduction indices

    __shared__ float bpx, bpy, bpz;  // broadcast of selected point

    const int b = blockIdx.x;
    const int t = threadIdx.x;
    const int lane = t & 31;
    const int wid  = t >> 5;

    const float* base = pts + (size_t)b * N * C;

    float x[K], y[K], z[K], d[K];
#pragma unroll
    for (int k = 0; k < K; ++k) {
        int i = t + k * 1024;
        const float* r = base + (size_t)i * C;
        x[k] = r[0]; y[k] = r[1]; z[k] = r[2];
        sx[i] = x[k]; sy[i] = y[k]; sz[i] = z[k];
    }
    __syncthreads();

    // initial distances: to point 0
    {
        float px = sx[0], py = sy[0], pz = sz[0];
#pragma unroll
        for (int k = 0; k < K; ++k) {
            float dx = x[k] - px, dy = y[k] - py, dz = z[k] - pz;
            d[k] = dx * dx + dy * dy + dz * dz;
        }
    }
    if (t == 0) idx_out[b * npoints] = 0;

    for (int it = 1; it < npoints; ++it) {
        // thread-local argmax (strict > keeps lowest global index: k ascending)
        float bv = d[0];
        int   bi = t;
#pragma unroll
        for (int k = 1; k < K; ++k) {
            int gi = t + k * 1024;
            if (d[k] > bv) { bv = d[k]; bi = gi; }
        }
        // warp reduce (value desc, index asc on ties)
#pragma unroll
        for (int o = 16; o > 0; o >>= 1) {
            float ov = __shfl_down_sync(0xffffffffu, bv, o);
            int   oi = __shfl_down_sync(0xffffffffu, bi, o);
            if (ov > bv || (ov == bv && oi < bi)) { bv = ov; bi = oi; }
        }
        if (lane == 0) { rv[wid] = bv; ri[wid] = bi; }
        __syncthreads();
        if (wid == 0) {
            bv = rv[lane]; bi = ri[lane];
#pragma unroll
            for (int o = 16; o > 0; o >>= 1) {
                float ov = __shfl_down_sync(0xffffffffu, bv, o);
                int   oi = __shfl_down_sync(0xffffffffu, bi, o);
                if (ov > bv || (ov == bv && oi < bi)) { bv = ov; bi = oi; }
            }
            if (lane == 0) {
                bpx = sx[bi]; bpy = sy[bi]; bpz = sz[bi];
                idx_out[b * npoints + it] = bi;
            }
        }
        __syncthreads();
        float px = bpx, py = bpy, pz = bpz;
#pragma unroll
        for (int k = 0; k < K; ++k) {
            float dx = x[k] - px, dy = y[k] - py, dz = z[k] - pz;
            float nd = dx * dx + dy * dy + dz * dz;
            d[k] = fminf(d[k], nd);
        }
    }
}

// ---------------------------------------------------------------------------
// Gather + pointwise 2-layer MLP + output assembly.
//   inp = gathered row (optionally duplicated), h = relu(inp@w1+b1),
//   feat = h@w2+b2, out_row = [xyz(3) | feat[3..F)]
// One (point, channel) pair per thread; 256 threads/block; point rows and
// hidden activations staged in shared memory; weights via L1.
// ---------------------------------------------------------------------------
template <int CPREV, int F, bool REPEAT>
__global__ __launch_bounds__(256)
void mlp_kernel(const float* __restrict__ in, const int* __restrict__ idx,
                const float* __restrict__ w1, const float* __restrict__ b1,
                const float* __restrict__ w2, const float* __restrict__ b2,
                float* __restrict__ out, int n_in, int npoints)
{
    constexpr int PPB = 256 / F;                 // points per block
    constexpr int CIN = REPEAT ? 2 * CPREV : CPREV;

    __shared__ float row[PPB][CPREV];
    __shared__ float hsm[PPB][F];

    const int t  = threadIdx.x;
    const int lp = t / F;
    const int g  = t % F;
    const int gp = blockIdx.x * PPB + lp;        // global point over B*npoints
    const int b  = gp / npoints;
    const int pt = gp % npoints;

    const int src = idx[b * npoints + pt];
    const float* r = in + ((size_t)b * n_in + src) * CPREV;
    if (g < CPREV) row[lp][g] = r[g];
    __syncthreads();

    float acc = b1[g];
#pragma unroll
    for (int c = 0; c < CIN; ++c)
        acc += row[lp][c % CPREV] * w1[c * F + g];
    hsm[lp][g] = fmaxf(acc, 0.0f);
    __syncthreads();

    float o = b2[g];
#pragma unroll
    for (int j = 0; j < F; ++j)
        o += hsm[lp][j] * w2[j * F + g];

    float* orow = out + ((size_t)b * npoints + pt) * F;
    orow[g] = (g < 3) ? row[lp][g] : o;
}

// ---------------------------------------------------------------------------
// Launch
// ---------------------------------------------------------------------------
extern "C" void kernel_launch(void* const* d_in, const int* in_sizes, int n_in_cnt,
                              void* d_out, int out_size)
{
    (void)in_sizes; (void)n_in_cnt; (void)out_size;

    const float* pts = (const float*)d_in[0];
    const float* w1_1 = (const float*)d_in[1];
    const float* b1_1 = (const float*)d_in[2];
    const float* w2_1 = (const float*)d_in[3];
    const float* b2_1 = (const float*)d_in[4];
    const float* w1_2 = (const float*)d_in[5];
    const float* b1_2 = (const float*)d_in[6];
    const float* w2_2 = (const float*)d_in[7];
    const float* b2_2 = (const float*)d_in[8];
    const float* w1_3 = (const float*)d_in[9];
    const float* b1_3 = (const float*)d_in[10];
    const float* w2_3 = (const float*)d_in[11];
    const float* b2_3 = (const float*)d_in[12];
    const float* w1_4 = (const float*)d_in[13];
    const float* b1_4 = (const float*)d_in[14];
    const float* w2_4 = (const float*)d_in[15];
    const float* b2_4 = (const float*)d_in[16];

    float* out = (float*)d_out;
    const int B = 8;
    float* f1 = out;                        // [8,4096,16]
    float* f2 = out + 8 * 4096 * 16;        // [8,2048,32]
    float* f3 = f2 + 8 * 2048 * 32;         // [8,1024,64]
    float* f4 = f3 + 8 * 1024 * 64;         // [8, 512,128]

    static int* idx_buf = nullptr;
    if (!idx_buf) cudaGetSymbolAddress((void**)&idx_buf, g_fps_idx);

    static bool attr_done = false;
    if (!attr_done) {
        cudaFuncSetAttribute(fps_kernel<8192, 8>,
                             cudaFuncAttributeMaxDynamicSharedMemorySize, 3 * 8192 * 4 + 512);
        cudaFuncSetAttribute(fps_kernel<4096, 4>,
                             cudaFuncAttributeMaxDynamicSharedMemorySize, 3 * 4096 * 4 + 512);
        cudaFuncSetAttribute(fps_kernel<2048, 2>,
                             cudaFuncAttributeMaxDynamicSharedMemorySize, 3 * 2048 * 4 + 512);
        cudaFuncSetAttribute(fps_kernel<1024, 1>,
                             cudaFuncAttributeMaxDynamicSharedMemorySize, 3 * 1024 * 4 + 512);
        attr_done = true;
    }

    // ---- Level 1: 8192 -> 4096, C=3 (repeat to 6), F=16 ----
    fps_kernel<8192, 8><<<B, 1024, 3 * 8192 * 4 + 512>>>(pts, 3, 4096, idx_buf);
    mlp_kernel<3, 16, true><<<(B * 4096) / 16, 256>>>(
        pts, idx_buf, w1_1, b1_1, w2_1, b2_1, f1, 8192, 4096);

    // ---- Level 2: 4096 -> 2048, C=16, F=32 ----
    fps_kernel<4096, 4><<<B, 1024, 3 * 4096 * 4 + 512>>>(f1, 16, 2048, idx_buf);
    mlp_kernel<16, 32, false><<<(B * 2048) / 8, 256>>>(
        f1, idx_buf, w1_2, b1_2, w2_2, b2_2, f2, 4096, 2048);

    // ---- Level 3: 2048 -> 1024, C=32, F=64 ----
    fps_kernel<2048, 2><<<B, 1024, 3 * 2048 * 4 + 512>>>(f2, 32, 1024, idx_buf);
    mlp_kernel<32, 64, false><<<(B * 1024) / 4, 256>>>(
        f2, idx_buf, w1_3, b1_3, w2_3, b2_3, f3, 2048, 1024);

    // ---- Level 4: 1024 -> 512, C=64, F=128 ----
    fps_kernel<1024, 1><<<B, 1024, 3 * 1024 * 4 + 512>>>(f3, 64, 512, idx_buf);
    mlp_kernel<64, 128, false><<<(B * 512) / 2, 256>>>(
        f3, idx_buf, w1_4, b1_4, w2_4, b2_4, f4, 1024, 512);
}

// round 3
// speedup vs baseline: 1.8310x; 1.8310x over previous
#include <cuda_runtime.h>
#include <cstdint>

// ---------------------------------------------------------------------------
// Scratch: FPS index buffer (max level-1 size: 8 batches x 4096 points)
// ---------------------------------------------------------------------------
__device__ int g_fps_idx[8 * 4096];

// ---------------------------------------------------------------------------
// Furthest point sampling. One block (1024 threads) per batch.
// Distance arithmetic is VERBATIM from the R1 kernel (bit-compatible with
// the JAX reference): dx = x - px; nd = dx*dx + dy*dy + dz*dz (nvcc
// contracts); d = fminf(d, nd); thread-local argmax with strict '>'
// (first-occurrence). Reduction uses redux.sync on float bits (distances
// are >= 0, so bit order == value order): max value bits, then min index
// among tied lanes -> exact jnp.argmax first-occurrence semantics.
// One __syncthreads per iteration via parity double-buffered warp slots;
// every warp redundantly performs stage 2 so the selected point's coords
// come straight from a float4 SMEM copy (one LDS.128).
// ---------------------------------------------------------------------------
template <int N, int K>
__global__ __launch_bounds__(1024, 1)
void fps_kernel(const float* __restrict__ pts, int C, int npoints,
                int* __restrict__ idx_out)
{
    extern __shared__ float4 sxyz[];          // N entries: (x,y,z,0)
    __shared__ unsigned rvu[2][32];
    __shared__ int      ri[2][32];

    const int b    = blockIdx.x;
    const int t    = threadIdx.x;
    const int lane = t & 31;
    const int wid  = t >> 5;

    const float* base = pts + (size_t)b * N * C;

    float x[K], y[K], z[K], d[K];

    // load coords -> registers + SMEM float4 copy
#pragma unroll
    for (int k = 0; k < K; ++k) {
        int i = t + k * 1024;
        const float* r = base + (size_t)i * C;
        x[k] = r[0]; y[k] = r[1]; z[k] = r[2];
        sxyz[i] = make_float4(x[k], y[k], z[k], 0.f);
    }
    __syncthreads();

    if (t == 0) idx_out[b * npoints] = 0;

    // initial distances to point 0 (same expression as R1)
    {
        float4 q = sxyz[0];
        float px = q.x, py = q.y, pz = q.z;
#pragma unroll
        for (int k = 0; k < K; ++k) {
            float dx = x[k] - px, dy = y[k] - py, dz = z[k] - pz;
            d[k] = dx * dx + dy * dy + dz * dz;
        }
    }

    // thread-local argmax of initial distances (strict > keeps lowest index)
    float bv = d[0];
    int   bi = t;
#pragma unroll
    for (int k = 1; k < K; ++k) {
        int gi = t + k * 1024;
        if (d[k] > bv) { bv = d[k]; bi = gi; }
    }

    for (int it = 1; it < npoints; ++it) {
        // stage 1: warp reduce via redux (max value bits, min index on ties)
        unsigned ub = __float_as_uint(bv);
        unsigned m1 = __reduce_max_sync(0xffffffffu, ub);
        unsigned c1 = (ub == m1) ? (unsigned)bi : 0x7fffffffu;
        unsigned i1 = __reduce_min_sync(0xffffffffu, c1);
        const int p = it & 1;
        if (lane == 0) { rvu[p][wid] = m1; ri[p][wid] = (int)i1; }
        __syncthreads();

        // stage 2: every warp reduces the 32 warp results redundantly
        unsigned vw = rvu[p][lane];
        int      iw = ri[p][lane];
        unsigned m2 = __reduce_max_sync(0xffffffffu, vw);
        unsigned c2 = (vw == m2) ? (unsigned)iw : 0x7fffffffu;
        int bsel = (int)__reduce_min_sync(0xffffffffu, c2);
        if (t == 0) idx_out[b * npoints + it] = bsel;

        float4 q = sxyz[bsel];                // LDS.128 broadcast
        float px = q.x, py = q.y, pz = q.z;

        // update distances + fused thread-local argmax (verbatim R1 math)
        bv = -1.0f; bi = 0;
#pragma unroll
        for (int k = 0; k < K; ++k) {
            float dx = x[k] - px, dy = y[k] - py, dz = z[k] - pz;
            float nd = dx * dx + dy * dy + dz * dz;
            float dk = fminf(d[k], nd);
            d[k] = dk;
            int gi = t + k * 1024;
            if (dk > bv) { bv = dk; bi = gi; }
        }
    }
}

// ---------------------------------------------------------------------------
// Gather + pointwise 2-layer MLP + output assembly (unchanged).
// ---------------------------------------------------------------------------
template <int CPREV, int F, bool REPEAT>
__global__ __launch_bounds__(256)
void mlp_kernel(const float* __restrict__ in, const int* __restrict__ idx,
                const float* __restrict__ w1, const float* __restrict__ b1,
                const float* __restrict__ w2, const float* __restrict__ b2,
                float* __restrict__ out, int n_in, int npoints)
{
    constexpr int PPB = 256 / F;
    constexpr int CIN = REPEAT ? 2 * CPREV : CPREV;

    __shared__ float row[PPB][CPREV];
    __shared__ float hsm[PPB][F];

    const int t  = threadIdx.x;
    const int lp = t / F;
    const int g  = t % F;
    const int gp = blockIdx.x * PPB + lp;
    const int b  = gp / npoints;
    const int pt = gp % npoints;

    const int src = idx[b * npoints + pt];
    const float* r = in + ((size_t)b * n_in + src) * CPREV;
    if (g < CPREV) row[lp][g] = r[g];
    __syncthreads();

    float acc = b1[g];
#pragma unroll
    for (int c = 0; c < CIN; ++c)
        acc += row[lp][c % CPREV] * w1[c * F + g];
    hsm[lp][g] = fmaxf(acc, 0.0f);
    __syncthreads();

    float o = b2[g];
#pragma unroll
    for (int j = 0; j < F; ++j)
        o += hsm[lp][j] * w2[j * F + g];

    float* orow = out + ((size_t)b * npoints + pt) * F;
    orow[g] = (g < 3) ? row[lp][g] : o;
}

// ---------------------------------------------------------------------------
// Launch
// ---------------------------------------------------------------------------
extern "C" void kernel_launch(void* const* d_in, const int* in_sizes, int n_in_cnt,
                              void* d_out, int out_size)
{
    (void)in_sizes; (void)n_in_cnt; (void)out_size;

    const float* pts  = (const float*)d_in[0];
    const float* w1_1 = (const float*)d_in[1];
    const float* b1_1 = (const float*)d_in[2];
    const float* w2_1 = (const float*)d_in[3];
    const float* b2_1 = (const float*)d_in[4];
    const float* w1_2 = (const float*)d_in[5];
    const float* b1_2 = (const float*)d_in[6];
    const float* w2_2 = (const float*)d_in[7];
    const float* b2_2 = (const float*)d_in[8];
    const float* w1_3 = (const float*)d_in[9];
    const float* b1_3 = (const float*)d_in[10];
    const float* w2_3 = (const float*)d_in[11];
    const float* b2_3 = (const float*)d_in[12];
    const float* w1_4 = (const float*)d_in[13];
    const float* b1_4 = (const float*)d_in[14];
    const float* w2_4 = (const float*)d_in[15];
    const float* b2_4 = (const float*)d_in[16];

    float* out = (float*)d_out;
    const int B = 8;
    float* f1 = out;                        // [8,4096,16]
    float* f2 = out + 8 * 4096 * 16;        // [8,2048,32]
    float* f3 = f2 + 8 * 2048 * 32;         // [8,1024,64]
    float* f4 = f3 + 8 * 1024 * 64;         // [8, 512,128]

    static int* idx_buf = nullptr;
    if (!idx_buf) cudaGetSymbolAddress((void**)&idx_buf, g_fps_idx);

    static bool attr_done = false;
    if (!attr_done) {
        cudaFuncSetAttribute(fps_kernel<8192, 8>,
                             cudaFuncAttributeMaxDynamicSharedMemorySize, 8192 * 16);
        cudaFuncSetAttribute(fps_kernel<4096, 4>,
                             cudaFuncAttributeMaxDynamicSharedMemorySize, 4096 * 16);
        cudaFuncSetAttribute(fps_kernel<2048, 2>,
                             cudaFuncAttributeMaxDynamicSharedMemorySize, 2048 * 16);
        cudaFuncSetAttribute(fps_kernel<1024, 1>,
                             cudaFuncAttributeMaxDynamicSharedMemorySize, 1024 * 16);
        attr_done = true;
    }

    // ---- Level 1: 8192 -> 4096, C=3 (repeat to 6), F=16 ----
    fps_kernel<8192, 8><<<B, 1024, 8192 * 16>>>(pts, 3, 4096, idx_buf);
    mlp_kernel<3, 16, true><<<(B * 4096) / 16, 256>>>(
        pts, idx_buf, w1_1, b1_1, w2_1, b2_1, f1, 8192, 4096);

    // ---- Level 2: 4096 -> 2048, C=16, F=32 ----
    fps_kernel<4096, 4><<<B, 1024, 4096 * 16>>>(f1, 16, 2048, idx_buf);
    mlp_kernel<16, 32, false><<<(B * 2048) / 8, 256>>>(
        f1, idx_buf, w1_2, b1_2, w2_2, b2_2, f2, 4096, 2048);

    // ---- Level 3: 2048 -> 1024, C=32, F=64 ----
    fps_kernel<2048, 2><<<B, 1024, 2048 * 16>>>(f2, 32, 1024, idx_buf);
    mlp_kernel<32, 64, false><<<(B * 1024) / 4, 256>>>(
        f2, idx_buf, w1_3, b1_3, w2_3, b2_3, f3, 2048, 1024);

    // ---- Level 4: 1024 -> 512, C=64, F=128 ----
    fps_kernel<1024, 1><<<B, 1024, 1024 * 16>>>(f3, 64, 512, idx_buf);
    mlp_kernel<64, 128, false><<<(B * 512) / 2, 256>>>(
        f3, idx_buf, w1_4, b1_4, w2_4, b2_4, f4, 1024, 512);
}